// round 7
// baseline (speedup 1.0000x reference)
#include <cuda_runtime.h>
#include <math.h>

#define BH 512
#define BW 512
#define BB 8
#define MAXT 160
#define TILE 64
#define NTHR 512
#define NBLOCKS ((BW/TILE)*(BH/TILE)*BB)   // 512

__device__ double g_acc[8];          // [cls*4 + {sumNo,cntNo,sumObj,cntObj}]
__device__ unsigned int g_ticket;

__device__ __forceinline__ float ex2f_(float x){ float y; asm("ex2.approx.f32 %0,%1;" : "=f"(y) : "f"(x)); return y; }
__device__ __forceinline__ float lg2f_(float x){ float y; asm("lg2.approx.f32 %0,%1;" : "=f"(y) : "f"(x)); return y; }
__device__ __forceinline__ float rcpf_(float x){ float y; asm("rcp.approx.f32 %0,%1;" : "=f"(y) : "f"(x)); return y; }

// ------------------------------------------------------------------
// One block = 64x64 tile. 512 threads x 8 px (2 row-passes of 4 px).
// ------------------------------------------------------------------
__global__ __launch_bounds__(NTHR, 2)
void fused_kernel(const float* __restrict__ pred,
                  const float* __restrict__ tgt, int nT,
                  float* __restrict__ out) {
    __shared__ float sc[2][6][MAXT];
    __shared__ int   nAct[2];
    __shared__ float sred[16][6];

    const int tid = threadIdx.x;
    const int b   = blockIdx.z;
    const int tx  = blockIdx.x * TILE;
    const int ty  = blockIdx.y * TILE;

    // ---- early pixel loads: 2 passes x 2 classes ----
    const int row = tid >> 4;          // 0..31
    const int col = (tid & 15) << 2;   // 0..60
    const size_t img = (size_t)BH * BW;
    const float* base0 = pred + (size_t)b * 2 * img + (size_t)(ty + row) * BW + (tx + col);
    float4 f0[2], f1[2];
    #pragma unroll
    for (int p = 0; p < 2; p++) {
        f0[p] = *(const float4*)(base0 + (size_t)p * 32 * BW);
        f1[p] = *(const float4*)(base0 + img + (size_t)p * 32 * BW);
    }

    if (tid < 2) nAct[tid] = 0;
    __syncthreads();

    // ---- target prologue: filter for this (batch, tile) ----
    const float gxlo = tx + 0.5f, gxhi = tx + TILE - 0.5f;
    const float gylo = ty + 0.5f, gyhi = ty + TILE - 0.5f;
    for (int i = tid; i < nT; i += NTHR) {
        const float* t = tgt + i * 7;
        if ((int)t[0] != b) continue;
        int   cls = (int)t[1];
        float cx = t[2] * 0.125f, cy = t[3] * 0.125f;
        float ww = t[4] * 0.125f, hh = t[5] * 0.125f;
        float c = __cosf(t[6]), s = __sinf(t[6]);
        float x =  cx * c + cy * s;
        float y = -cx * s + cy * c;
        float X3 = x - hh * 0.5f, X4 = x + hh * 0.5f;
        float Y3 = y - ww * 0.5f, Y4 = y + ww * 0.5f;
        float vxmin = fminf(c * gxlo, c * gxhi) + fminf(s * gylo, s * gyhi);
        float vxmax = fmaxf(c * gxlo, c * gxhi) + fmaxf(s * gylo, s * gyhi);
        float vymin = fminf(-s * gxlo, -s * gxhi) + fminf(c * gylo, c * gyhi);
        float vymax = fmaxf(-s * gxlo, -s * gxhi) + fmaxf(c * gylo, c * gyhi);
        if (vxmax >= X3 - 0.5f && vxmin <= X4 + 0.5f &&
            vymax >= Y3 - 0.5f && vymin <= Y4 + 0.5f) {
            int p = atomicAdd(&nAct[cls], 1);
            sc[cls][0][p] = c;  sc[cls][1][p] = s;
            sc[cls][2][p] = X3; sc[cls][3][p] = X4;
            sc[cls][4][p] = Y3; sc[cls][5][p] = Y4;
        }
    }
    __syncthreads();
    const int n0 = nAct[0], n1 = nAct[1];
    const bool hasT = (n0 | n1) != 0;

    const float LOG2E = 1.4426950408889634f;
    const float LN2   = 0.6931471805599453f;
    const float gx0   = tx + col + 0.5f;
    float* hout = out + 1 + (size_t)b * img + (size_t)(ty + row) * BW + (tx + col);

    float a0 = 0.f, o0 = 0.f, a1 = 0.f, o1 = 0.f;
    unsigned nc = 0u, oc = 0u;   // 16-bit fields [cls0 | cls1<<16], per-lane <=8

    #pragma unroll
    for (int p = 0; p < 2; p++) {
        const float4 F0 = f0[p], F1 = f1[p];
        float xl0[4] = {F0.x * LOG2E, F0.y * LOG2E, F0.z * LOG2E, F0.w * LOG2E};
        float xl1[4] = {F1.x * LOG2E, F1.y * LOG2E, F1.z * LOG2E, F1.w * LOG2E};
        float t0[4], t1[4];
        #pragma unroll
        for (int k = 0; k < 4; k++) { t0[k] = ex2f_(xl0[k]); t1[k] = ex2f_(xl1[k]); }

        // ---- masks (zero when tile has no targets) ----
        unsigned m0 = 0, m1 = 0;   // bits: obj=k, out=4+k
        if (hasT) {
            const float gy = ty + p * 32 + row + 0.5f;
            for (int j = 0; j < n0; j++) {
                float c  = sc[0][0][j], s  = sc[0][1][j];
                float X3 = sc[0][2][j], X4 = sc[0][3][j];
                float Y3 = sc[0][4][j], Y4 = sc[0][5][j];
                float sgy = s * gy, cgy = c * gy;
                #pragma unroll
                for (int k = 0; k < 4; k++) {
                    float gx = gx0 + (float)k;
                    float vx = fmaf(c, gx, sgy);
                    float vy = fmaf(-s, gx, cgy);
                    unsigned in_ = (vx >= X3) & (vx <= X4) & (vy >= Y3) & (vy <= Y4);
                    unsigned ot_ = (vx >= X3 - 0.5f) & (vx <= X4 + 0.5f) &
                                   (vy >= Y3 - 0.5f) & (vy <= Y4 + 0.5f);
                    m0 |= (in_ << k) | (ot_ << (4 + k));
                }
            }
            for (int j = 0; j < n1; j++) {
                float c  = sc[1][0][j], s  = sc[1][1][j];
                float X3 = sc[1][2][j], X4 = sc[1][3][j];
                float Y3 = sc[1][4][j], Y4 = sc[1][5][j];
                float sgy = s * gy, cgy = c * gy;
                #pragma unroll
                for (int k = 0; k < 4; k++) {
                    float gx = gx0 + (float)k;
                    float vx = fmaf(c, gx, sgy);
                    float vy = fmaf(-s, gx, cgy);
                    unsigned in_ = (vx >= X3) & (vx <= X4) & (vy >= Y3) & (vy <= Y4);
                    unsigned ot_ = (vx >= X3 - 0.5f) & (vx <= X4 + 0.5f) &
                                   (vy >= Y3 - 0.5f) & (vy <= Y4 + 0.5f);
                    m1 |= (in_ << k) | (ot_ << (4 + k));
                }
            }
        }

        // ---- heatmap: batched reciprocal (1 RCP per 4 px), SCALAR stores
        //      (out+1 base is 4-byte offset => STG.128 would trap) ----
        float tm[4], d[4];
        #pragma unroll
        for (int k = 0; k < 4; k++) { tm[k] = fmaxf(t0[k], t1[k]); d[k] = 1.0f + tm[k]; }
        float p01 = d[0] * d[1], p23 = d[2] * d[3];
        float R   = rcpf_(p01 * p23);
        float r01 = R * p23, r23 = R * p01;
        float* hp = hout + (size_t)p * 32 * BW;
        hp[0] = tm[0] * (r01 * d[1]);
        hp[1] = tm[1] * (r01 * d[0]);
        hp[2] = tm[2] * (r23 * d[3]);
        hp[3] = tm[3] * (r23 * d[2]);

        if ((m0 | m1) == 0u) {
            // ---- pure noobj group: 1 LG2 per class for all 4 px ----
            float P0 = (1.0f + t0[0]) * (1.0f + t0[1]) * (1.0f + t0[2]) * (1.0f + t0[3]);
            float P1 = (1.0f + t1[0]) * (1.0f + t1[1]) * (1.0f + t1[2]) * (1.0f + t1[3]);
            a0 += lg2f_(P0);
            a1 += lg2f_(P1);
            nc += 4u | (4u << 16);
        } else {
            // ---- mixed group: per-pixel path ----
            #pragma unroll
            for (int k = 0; k < 4; k++) {
                float L0 = lg2f_(1.0f + t0[k]);
                float L1 = lg2f_(1.0f + t1[k]);
                unsigned ob0 =  (m0 >> k) & 1u;
                unsigned no0 = ((~m0) >> (4 + k)) & 1u;
                unsigned ob1 =  (m1 >> k) & 1u;
                unsigned no1 = ((~m1) >> (4 + k)) & 1u;
                if (no0) a0 += L0;
                if (ob0) o0 += L0 - xl0[k];
                if (no1) a1 += L1;
                if (ob1) o1 += L1 - xl1[k];
                nc += no0 | (no1 << 16);
                oc += ob0 | (ob1 << 16);
            }
        }
    }

    // ---- block reduction ----
    #pragma unroll
    for (int off = 16; off; off >>= 1) {
        a0 += __shfl_down_sync(0xffffffffu, a0, off);
        o0 += __shfl_down_sync(0xffffffffu, o0, off);
        a1 += __shfl_down_sync(0xffffffffu, a1, off);
        o1 += __shfl_down_sync(0xffffffffu, o1, off);
        nc += __shfl_down_sync(0xffffffffu, nc, off);  // per-warp field <=256, fits 16b
        oc += __shfl_down_sync(0xffffffffu, oc, off);
    }
    const int wid = tid >> 5;
    if ((tid & 31) == 0) {
        sred[wid][0] = a0; sred[wid][1] = o0;
        sred[wid][2] = a1; sred[wid][3] = o1;
        sred[wid][4] = __uint_as_float(nc);
        sred[wid][5] = __uint_as_float(oc);
    }
    __syncthreads();
    if (tid < 4) {
        float ssum = 0.f;
        #pragma unroll
        for (int wv = 0; wv < 16; wv++) ssum += sred[wv][tid];
        // 0->sumNo0(g_acc[0]) 1->sumOb0(g_acc[2]) 2->sumNo1(g_acc[4]) 3->sumOb1(g_acc[6])
        if (ssum != 0.f) atomicAdd(&g_acc[tid * 2], (double)(ssum * LN2));
    } else if (tid == 4) {
        unsigned cNo0 = 0, cNo1 = 0;
        #pragma unroll
        for (int wv = 0; wv < 16; wv++) {
            unsigned cw = __float_as_uint(sred[wv][4]);
            cNo0 += cw & 0xffffu; cNo1 += cw >> 16;
        }
        if (cNo0) atomicAdd(&g_acc[1], (double)cNo0);
        if (cNo1) atomicAdd(&g_acc[5], (double)cNo1);
    } else if (tid == 5) {
        unsigned cOb0 = 0, cOb1 = 0;
        #pragma unroll
        for (int wv = 0; wv < 16; wv++) {
            unsigned cw = __float_as_uint(sred[wv][5]);
            cOb0 += cw & 0xffffu; cOb1 += cw >> 16;
        }
        if (cOb0) atomicAdd(&g_acc[3], (double)cOb0);
        if (cOb1) atomicAdd(&g_acc[7], (double)cOb1);
    }
    if (tid < 6) __threadfence();
    __syncthreads();

    // ---- last-block election: finalize scalar loss, self-clean ----
    if (tid == 0) {
        unsigned int ticket = atomicAdd(&g_ticket, 1u);
        if (ticket == NBLOCKS - 1) {
            __threadfence();
            double a[8];
            #pragma unroll
            for (int j = 0; j < 8; j++)
                a[j] = *((volatile double*)&g_acc[j]);
            double loss = 0.0;
            #pragma unroll
            for (int cls = 0; cls < 2; cls++) {
                double sNo = a[cls * 4 + 0], cNo = a[cls * 4 + 1];
                double sOb = a[cls * 4 + 2], cOb = a[cls * 4 + 3];
                if (cOb > 0.0)
                    loss += sOb / fmax(cOb, 1.0) + sNo / fmax(cNo, 1.0);
            }
            out[0] = (float)loss;
            #pragma unroll
            for (int j = 0; j < 8; j++) g_acc[j] = 0.0;
            g_ticket = 0u;
            __threadfence();
        }
    }
}

// ------------------------------------------------------------------
extern "C" void kernel_launch(void* const* d_in, const int* in_sizes, int n_in,
                              void* d_out, int out_size) {
    const float* pred = (const float*)d_in[0];
    const float* tgt  = (const float*)d_in[1];
    int nT = in_sizes[1] / 7;
    float* out = (float*)d_out;

    dim3 grid(BW / TILE, BH / TILE, BB);
    fused_kernel<<<grid, NTHR>>>(pred, tgt, nT, out);
}

// round 8
// speedup vs baseline: 1.1174x; 1.1174x over previous
#include <cuda_runtime.h>
#include <math.h>

#define BH 512
#define BW 512
#define BB 8
#define MAXT 160
#define TILE 64
#define NTHR 256
#define NBLOCKS ((BW/TILE)*(BH/TILE)*BB)   // 512

__device__ double g_acc[8];          // [cls*4 + {sumNo,cntNo,sumObj,cntObj}]
__device__ unsigned int g_ticket;

__device__ __forceinline__ float ex2f_(float x){ float y; asm("ex2.approx.f32 %0,%1;" : "=f"(y) : "f"(x)); return y; }
__device__ __forceinline__ float lg2f_(float x){ float y; asm("lg2.approx.f32 %0,%1;" : "=f"(y) : "f"(x)); return y; }
__device__ __forceinline__ float rcpf_(float x){ float y; asm("rcp.approx.f32 %0,%1;" : "=f"(y) : "f"(x)); return y; }

// ------------------------------------------------------------------
// One block = 64x64 tile. 256 threads x 16 px (4 row-passes of 4 px).
// Single wave: 512 CTAs, 4 CTAs/SM x 148 SMs = 592 slots.
// ------------------------------------------------------------------
__global__ __launch_bounds__(NTHR, 4)
void fused_kernel(const float* __restrict__ pred,
                  const float* __restrict__ tgt, int nT,
                  float* __restrict__ out) {
    __shared__ float sc[2][6][MAXT];
    __shared__ int   nAct[2];
    __shared__ float sred[8][6];

    const int tid = threadIdx.x;
    const int b   = blockIdx.z;
    const int tx  = blockIdx.x * TILE;
    const int ty  = blockIdx.y * TILE;

    // ---- early pixel loads: 4 passes x 2 classes (MLP=8) ----
    const int row = tid >> 4;          // 0..15
    const int col = (tid & 15) << 2;   // 0..60
    const size_t img = (size_t)BH * BW;
    const float* base0 = pred + (size_t)b * 2 * img + (size_t)(ty + row) * BW + (tx + col);
    float4 f0[4], f1[4];
    #pragma unroll
    for (int p = 0; p < 4; p++) {
        f0[p] = *(const float4*)(base0 + (size_t)p * 16 * BW);
        f1[p] = *(const float4*)(base0 + img + (size_t)p * 16 * BW);
    }

    if (tid < 2) nAct[tid] = 0;
    __syncthreads();

    // ---- target prologue: filter for this (batch, tile) ----
    const float gxlo = tx + 0.5f, gxhi = tx + TILE - 0.5f;
    const float gylo = ty + 0.5f, gyhi = ty + TILE - 0.5f;
    for (int i = tid; i < nT; i += NTHR) {
        const float* t = tgt + i * 7;
        if ((int)t[0] != b) continue;
        int   cls = (int)t[1];
        float cx = t[2] * 0.125f, cy = t[3] * 0.125f;
        float ww = t[4] * 0.125f, hh = t[5] * 0.125f;
        float c = __cosf(t[6]), s = __sinf(t[6]);
        float x =  cx * c + cy * s;
        float y = -cx * s + cy * c;
        float X3 = x - hh * 0.5f, X4 = x + hh * 0.5f;
        float Y3 = y - ww * 0.5f, Y4 = y + ww * 0.5f;
        float vxmin = fminf(c * gxlo, c * gxhi) + fminf(s * gylo, s * gyhi);
        float vxmax = fmaxf(c * gxlo, c * gxhi) + fmaxf(s * gylo, s * gyhi);
        float vymin = fminf(-s * gxlo, -s * gxhi) + fminf(c * gylo, c * gyhi);
        float vymax = fmaxf(-s * gxlo, -s * gxhi) + fmaxf(c * gylo, c * gyhi);
        if (vxmax >= X3 - 0.5f && vxmin <= X4 + 0.5f &&
            vymax >= Y3 - 0.5f && vymin <= Y4 + 0.5f) {
            int p = atomicAdd(&nAct[cls], 1);
            sc[cls][0][p] = c;  sc[cls][1][p] = s;
            sc[cls][2][p] = X3; sc[cls][3][p] = X4;
            sc[cls][4][p] = Y3; sc[cls][5][p] = Y4;
        }
    }
    __syncthreads();
    const int n0 = nAct[0], n1 = nAct[1];
    const bool hasT = (n0 | n1) != 0;

    const float LOG2E = 1.4426950408889634f;
    const float LN2   = 0.6931471805599453f;
    const float gx0   = tx + col + 0.5f;
    float* hout = out + 1 + (size_t)b * img + (size_t)(ty + row) * BW + (tx + col);

    float a0 = 0.f, o0 = 0.f, a1 = 0.f, o1 = 0.f;
    unsigned nc = 0u, oc = 0u;   // 16-bit fields [cls0 | cls1<<16], per-lane <=16

    #pragma unroll
    for (int p = 0; p < 4; p++) {
        const float4 F0 = f0[p], F1 = f1[p];
        float xl0[4] = {F0.x * LOG2E, F0.y * LOG2E, F0.z * LOG2E, F0.w * LOG2E};
        float xl1[4] = {F1.x * LOG2E, F1.y * LOG2E, F1.z * LOG2E, F1.w * LOG2E};
        float t0[4], t1[4];
        #pragma unroll
        for (int k = 0; k < 4; k++) { t0[k] = ex2f_(xl0[k]); t1[k] = ex2f_(xl1[k]); }

        // ---- masks (zero when tile has no targets) ----
        unsigned m0 = 0, m1 = 0;   // bits: obj=k, out=4+k
        if (hasT) {
            const float gy = ty + p * 16 + row + 0.5f;
            for (int j = 0; j < n0; j++) {
                float c  = sc[0][0][j], s  = sc[0][1][j];
                float X3 = sc[0][2][j], X4 = sc[0][3][j];
                float Y3 = sc[0][4][j], Y4 = sc[0][5][j];
                float sgy = s * gy, cgy = c * gy;
                #pragma unroll
                for (int k = 0; k < 4; k++) {
                    float gx = gx0 + (float)k;
                    float vx = fmaf(c, gx, sgy);
                    float vy = fmaf(-s, gx, cgy);
                    unsigned in_ = (vx >= X3) & (vx <= X4) & (vy >= Y3) & (vy <= Y4);
                    unsigned ot_ = (vx >= X3 - 0.5f) & (vx <= X4 + 0.5f) &
                                   (vy >= Y3 - 0.5f) & (vy <= Y4 + 0.5f);
                    m0 |= (in_ << k) | (ot_ << (4 + k));
                }
            }
            for (int j = 0; j < n1; j++) {
                float c  = sc[1][0][j], s  = sc[1][1][j];
                float X3 = sc[1][2][j], X4 = sc[1][3][j];
                float Y3 = sc[1][4][j], Y4 = sc[1][5][j];
                float sgy = s * gy, cgy = c * gy;
                #pragma unroll
                for (int k = 0; k < 4; k++) {
                    float gx = gx0 + (float)k;
                    float vx = fmaf(c, gx, sgy);
                    float vy = fmaf(-s, gx, cgy);
                    unsigned in_ = (vx >= X3) & (vx <= X4) & (vy >= Y3) & (vy <= Y4);
                    unsigned ot_ = (vx >= X3 - 0.5f) & (vx <= X4 + 0.5f) &
                                   (vy >= Y3 - 0.5f) & (vy <= Y4 + 0.5f);
                    m1 |= (in_ << k) | (ot_ << (4 + k));
                }
            }
        }

        // ---- heatmap: batched reciprocal (1 RCP per 4 px), scalar stores ----
        float tm[4], d[4];
        #pragma unroll
        for (int k = 0; k < 4; k++) { tm[k] = fmaxf(t0[k], t1[k]); d[k] = 1.0f + tm[k]; }
        float p01 = d[0] * d[1], p23 = d[2] * d[3];
        float R   = rcpf_(p01 * p23);
        float r01 = R * p23, r23 = R * p01;
        float* hp = hout + (size_t)p * 16 * BW;
        hp[0] = tm[0] * (r01 * d[1]);
        hp[1] = tm[1] * (r01 * d[0]);
        hp[2] = tm[2] * (r23 * d[3]);
        hp[3] = tm[3] * (r23 * d[2]);

        if ((m0 | m1) == 0u) {
            // ---- pure noobj group: 1 LG2 per class for 4 px ----
            float P0 = (1.0f + t0[0]) * (1.0f + t0[1]) * (1.0f + t0[2]) * (1.0f + t0[3]);
            float P1 = (1.0f + t1[0]) * (1.0f + t1[1]) * (1.0f + t1[2]) * (1.0f + t1[3]);
            a0 += lg2f_(P0);
            a1 += lg2f_(P1);
            nc += 4u | (4u << 16);
        } else {
            // ---- mixed group: per-pixel path ----
            #pragma unroll
            for (int k = 0; k < 4; k++) {
                float L0 = lg2f_(1.0f + t0[k]);
                float L1 = lg2f_(1.0f + t1[k]);
                unsigned ob0 =  (m0 >> k) & 1u;
                unsigned no0 = ((~m0) >> (4 + k)) & 1u;
                unsigned ob1 =  (m1 >> k) & 1u;
                unsigned no1 = ((~m1) >> (4 + k)) & 1u;
                if (no0) a0 += L0;
                if (ob0) o0 += L0 - xl0[k];
                if (no1) a1 += L1;
                if (ob1) o1 += L1 - xl1[k];
                nc += no0 | (no1 << 16);
                oc += ob0 | (ob1 << 16);
            }
        }
    }

    // ---- block reduction: floats via shuffle, counts via REDUX ----
    #pragma unroll
    for (int off = 16; off; off >>= 1) {
        a0 += __shfl_down_sync(0xffffffffu, a0, off);
        o0 += __shfl_down_sync(0xffffffffu, o0, off);
        a1 += __shfl_down_sync(0xffffffffu, a1, off);
        o1 += __shfl_down_sync(0xffffffffu, o1, off);
    }
    nc = __reduce_add_sync(0xffffffffu, nc);   // per-warp field <=512, fits 16b
    oc = __reduce_add_sync(0xffffffffu, oc);
    const int wid = tid >> 5;
    if ((tid & 31) == 0) {
        sred[wid][0] = a0; sred[wid][1] = o0;
        sred[wid][2] = a1; sred[wid][3] = o1;
        sred[wid][4] = __uint_as_float(nc);
        sred[wid][5] = __uint_as_float(oc);
    }
    __syncthreads();
    if (tid < 4) {
        float ssum = 0.f;
        #pragma unroll
        for (int wv = 0; wv < 8; wv++) ssum += sred[wv][tid];
        // 0->sumNo0(g_acc[0]) 1->sumOb0(g_acc[2]) 2->sumNo1(g_acc[4]) 3->sumOb1(g_acc[6])
        if (ssum != 0.f) atomicAdd(&g_acc[tid * 2], (double)(ssum * LN2));
    } else if (tid == 4) {
        unsigned cNo0 = 0, cNo1 = 0;
        #pragma unroll
        for (int wv = 0; wv < 8; wv++) {
            unsigned cw = __float_as_uint(sred[wv][4]);
            cNo0 += cw & 0xffffu; cNo1 += cw >> 16;
        }
        if (cNo0) atomicAdd(&g_acc[1], (double)cNo0);
        if (cNo1) atomicAdd(&g_acc[5], (double)cNo1);
    } else if (tid == 5) {
        unsigned cOb0 = 0, cOb1 = 0;
        #pragma unroll
        for (int wv = 0; wv < 8; wv++) {
            unsigned cw = __float_as_uint(sred[wv][5]);
            cOb0 += cw & 0xffffu; cOb1 += cw >> 16;
        }
        if (cOb0) atomicAdd(&g_acc[3], (double)cOb0);
        if (cOb1) atomicAdd(&g_acc[7], (double)cOb1);
    }
    if (tid < 6) __threadfence();
    __syncthreads();

    // ---- last-block election: finalize scalar loss, self-clean ----
    if (tid == 0) {
        unsigned int ticket = atomicAdd(&g_ticket, 1u);
        if (ticket == NBLOCKS - 1) {
            __threadfence();
            double a[8];
            #pragma unroll
            for (int j = 0; j < 8; j++)
                a[j] = *((volatile double*)&g_acc[j]);
            double loss = 0.0;
            #pragma unroll
            for (int cls = 0; cls < 2; cls++) {
                double sNo = a[cls * 4 + 0], cNo = a[cls * 4 + 1];
                double sOb = a[cls * 4 + 2], cOb = a[cls * 4 + 3];
                if (cOb > 0.0)
                    loss += sOb / fmax(cOb, 1.0) + sNo / fmax(cNo, 1.0);
            }
            out[0] = (float)loss;
            #pragma unroll
            for (int j = 0; j < 8; j++) g_acc[j] = 0.0;
            g_ticket = 0u;
            __threadfence();
        }
    }
}

// ------------------------------------------------------------------
extern "C" void kernel_launch(void* const* d_in, const int* in_sizes, int n_in,
                              void* d_out, int out_size) {
    const float* pred = (const float*)d_in[0];
    const float* tgt  = (const float*)d_in[1];
    int nT = in_sizes[1] / 7;
    float* out = (float*)d_out;

    dim3 grid(BW / TILE, BH / TILE, BB);
    fused_kernel<<<grid, NTHR>>>(pred, tgt, nT, out);
}